// round 13
// baseline (speedup 1.0000x reference)
#include <cuda_runtime.h>
#include <math.h>

// ---------------------------------------------------------------------------
// Problem dims (fixed by dataset): V=1024, E=256, H=512, B=64, S=2048
// ---------------------------------------------------------------------------
constexpr int Sn = 2048;
constexpr int Bn = 64;
constexpr int Hn = 512;
constexpr int En = 256;
constexpr int Vn = 1024;

constexpr int SEQ_ELEMS = Sn * Bn * Hn;        // 67,108,864 floats (256 MB)

// Scan: 16 batch-groups x 8-CTA clusters. CTA = 4 b-rows x 64 j-cols.
constexpr int SCAN_CTAS  = 128;
constexpr int WS_FLOATS  = 64 * 516;           // Whh slice, padded pitch
constexpr int HS_FLOATS  = 4 * 516;            // one h buffer (4 rows, 512 used)
constexpr int SCAN_SMEM  = (WS_FLOATS + 2 * HS_FLOATS) * 4;   // 148,608 B

// Device-global scratch (allocation-free per harness rules)
__device__ float g_T[Vn * Hn];                 // emb @ Wxh0^T + bxh0 + bhh0
__device__ float g_seq0[SEQ_ELEMS];            // h0 sequence, reused as h1 seq
__device__ float g_A1[SEQ_ELEMS];              // layer-1 precomputed input term

// ---------------------------------------------------------------------------
// Packed fp32x2 FMA helpers
// ---------------------------------------------------------------------------
__device__ __forceinline__ void fma2(unsigned long long& d,
                                     unsigned long long a,
                                     unsigned long long b) {
    asm("fma.rn.f32x2 %0, %1, %2, %0;" : "+l"(d) : "l"(a), "l"(b));
}
__device__ __forceinline__ unsigned long long pack2(float lo, float hi) {
    unsigned long long r;
    asm("mov.b64 %0, {%1, %2};" : "=l"(r) : "f"(lo), "f"(hi));
    return r;
}
__device__ __forceinline__ float2 unpack2(unsigned long long v) {
    float2 r;
    asm("mov.b64 {%0, %1}, %2;" : "=f"(r.x), "=f"(r.y) : "l"(v));
    return r;
}

// ---------------------------------------------------------------------------
// Cluster / DSMEM primitives (sm_90 baseline PTX — legal on plain sm_103)
// ---------------------------------------------------------------------------
__device__ __forceinline__ unsigned smem_u32(const void* p) {
    unsigned a;
    asm("{ .reg .u64 t; cvta.to.shared.u64 t, %1; cvt.u32.u64 %0, t; }"
        : "=r"(a) : "l"(p));
    return a;
}
__device__ __forceinline__ unsigned cluster_rank() {
    unsigned r;
    asm("mov.u32 %0, %%cluster_ctarank;" : "=r"(r));
    return r;
}
// Store one float into the smem of cluster CTA `rank` at local-equivalent addr.
__device__ __forceinline__ void sts_cluster(unsigned laddr, unsigned rank,
                                            float v) {
    asm volatile("{\n\t.reg .b32 ra;\n\t"
                 "mapa.shared::cluster.u32 ra, %0, %1;\n\t"
                 "st.shared::cluster.f32 [ra], %2;\n\t}"
                 :: "r"(laddr), "r"(rank), "f"(v) : "memory");
}
#define CLUSTER_SYNC() do {                                            \
    asm volatile("barrier.cluster.arrive.aligned;" ::: "memory");      \
    asm volatile("barrier.cluster.wait.aligned;"   ::: "memory");      \
} while (0)

// ---------------------------------------------------------------------------
// T[v][j] = sum_e emb[v][e] * Wxh0[j][e] + bxh0[j] + bhh0[j]
// ---------------------------------------------------------------------------
__global__ void __launch_bounds__(256) build_table(
    const float* __restrict__ emb, const float* __restrict__ Wxh0,
    const float* __restrict__ bxh0, const float* __restrict__ bhh0)
{
    __shared__ float es[En];
    const int v = blockIdx.x;
    const int tid = threadIdx.x;
    es[tid] = emb[(size_t)v * En + tid];
    __syncthreads();
    #pragma unroll
    for (int jj = 0; jj < 2; jj++) {
        const int j = tid + jj * 256;
        const float4* w = (const float4*)(Wxh0 + (size_t)j * En);
        float s = 0.0f;
        #pragma unroll 16
        for (int k = 0; k < En / 4; k++) {
            float4 wv = __ldg(&w[k]);
            s = fmaf(wv.x, es[4 * k + 0], s);
            s = fmaf(wv.y, es[4 * k + 1], s);
            s = fmaf(wv.z, es[4 * k + 2], s);
            s = fmaf(wv.w, es[4 * k + 3], s);
        }
        g_T[(size_t)v * Hn + j] = s + bxh0[j] + bhh0[j];
    }
}

// ---------------------------------------------------------------------------
// Cluster-resident recurrent scan.
// Cluster (8 CTAs) = batch group grp = blockIdx.x>>3 -> rows b0 = grp*4.
// CTA rank r owns j-slice j0 = r*64; its 64 Whh rows live in smem all scan.
// h lives ONLY in smem: double-buffered [2][4][516]. Each step every thread
// pushes its y into all 8 CTAs' next-buffer via st.shared::cluster, then one
// cluster.sync (release/acquire) publishes it. No L2 traffic, no atomics.
// Thread map: warp w -> jj = w*8 + (l&7), bi = l>>3 (8 j x 4 b per warp).
// ---------------------------------------------------------------------------
__global__ void __launch_bounds__(256, 1) __cluster_dims__(8, 1, 1)
rnn_scan(
    const float* __restrict__ Whh,     // [512][512] (out j, in k)
    int mode,
    const int*   __restrict__ x,       // [B][S]      (mode 0)
    const float* __restrict__ T,       // [V][H]      (mode 0)
    const float* __restrict__ A1,      // [S][B][H]   (mode 1)
    float* __restrict__ hseq,          // [S][B][H]
    float* __restrict__ hfinal)        // [B][H]
{
    extern __shared__ float sm[];
    float* Ws   = sm;                  // [64][516]
    float* hbuf = sm + WS_FLOATS;      // [2][4][516]

    const unsigned rank = cluster_rank();     // 0..7
    const int grp = blockIdx.x >> 3;          // 0..15
    const int b0  = grp * 4;
    const int j0  = (int)rank * 64;
    const int tid = threadIdx.x;
    const int w   = tid >> 5;
    const int l   = tid & 31;
    const int jj  = w * 8 + (l & 7);          // 0..63
    const int bi  = l >> 3;                   // 0..3
    const int b   = b0 + bi;
    const int j   = j0 + jj;                  // global h index 0..511
    const unsigned hb_u32 = smem_u32(hbuf);

    // Prologue: zero h buffer 0; load this CTA's 64 Whh rows (float4)
    for (int i = tid; i < HS_FLOATS; i += 256) hbuf[i] = 0.0f;
    for (int i = tid; i < 64 * 128; i += 256) {
        const int r  = i >> 7;
        const int c4 = (i & 127) << 2;
        *(float4*)(Ws + r * 516 + c4) =
            __ldg((const float4*)(Whh + (size_t)(j0 + r) * Hn + c4));
    }
    CLUSTER_SYNC();   // smem ready cluster-wide before any DSMEM traffic

    for (int t = 0; t < Sn; t++) {
        // Input term (independent of h; issued first)
        float base;
        if (mode == 0) {
            const int xv = x[(size_t)b * Sn + t];
            base = __ldg(&T[(size_t)xv * Hn + j]);
        } else {
            base = __ldcs(&A1[((size_t)t * Bn + b) * Hn + j]);
        }

        const float* hs_cur = hbuf + (t & 1) * HS_FLOATS;
        const ulonglong2* hp = (const ulonglong2*)(hs_cur + bi * 516);
        const ulonglong2* wp = (const ulonglong2*)(Ws + jj * 516);
        unsigned long long s01 = 0ull, s23 = 0ull;
        #pragma unroll 16
        for (int k = 0; k < Hn / 4; k++) {
            ulonglong2 hv = hp[k];
            ulonglong2 wv = wp[k];
            fma2(s01, hv.x, wv.x);
            fma2(s23, hv.y, wv.y);
        }
        const float2 p0 = unpack2(s01);
        const float2 p1 = unpack2(s23);
        const float y = tanhf(((p0.x + p0.y) + (p1.x + p1.y)) + base);

        hseq[((size_t)t * Bn + b) * Hn + j] = y;
        if (t == Sn - 1) hfinal[(size_t)b * Hn + j] = y;

        // Broadcast y into every cluster CTA's next h buffer (incl. self)
        const unsigned laddr =
            hb_u32 + ((unsigned)(((t + 1) & 1) * HS_FLOATS + bi * 516 + j) << 2);
        #pragma unroll
        for (unsigned r = 0; r < 8; r++) sts_cluster(laddr, r, y);

        CLUSTER_SYNC();   // release our stores / acquire peers' stores
    }
}

// ---------------------------------------------------------------------------
// SGEMM: C[M,N] = A[M,K] @ B[N,K]^T + bias1[n] (+ bias2[n])
// 128x128 tile, BK=16, 256 threads, 8x8 microtile via FFMA2, 2 blocks/SM.
// permuteOut: remap row r (= t*B + b) -> out row b*S + t  (logits layout).
// ---------------------------------------------------------------------------
__global__ void __launch_bounds__(256, 2) sgemm_bt(
    const float* __restrict__ A, const float* __restrict__ Bm,
    const float* __restrict__ bias1, const float* __restrict__ bias2,
    float* __restrict__ C, int M, int N, int K, int permuteOut)
{
    __shared__ float As[16][128];
    __shared__ float Bs[16][128];

    const int tid  = threadIdx.x;
    const int tx   = tid & 15;          // 0..15 -> 8 cols each
    const int ty   = tid >> 4;          // 0..15 -> 8 rows each
    const int row0 = blockIdx.y * 128;
    const int col0 = blockIdx.x * 128;

    const int aRow = tid >> 1;          // 0..127
    const int aK8  = (tid & 1) * 8;     // 0 or 8
    const float* Ag = A  + (size_t)(row0 + aRow) * K + aK8;
    const float* Bg = Bm + (size_t)(col0 + aRow) * K + aK8;

    unsigned long long acc2[8][4] = {};  // 8 rows x 4 packed col-pairs

    for (int k0 = 0; k0 < K; k0 += 16) {
        const float4 av0 = __ldg((const float4*)(Ag + k0));
        const float4 av1 = __ldg((const float4*)(Ag + k0 + 4));
        const float4 bv0 = __ldg((const float4*)(Bg + k0));
        const float4 bv1 = __ldg((const float4*)(Bg + k0 + 4));
        __syncthreads();                // previous tile fully consumed
        As[aK8 + 0][aRow] = av0.x; As[aK8 + 1][aRow] = av0.y;
        As[aK8 + 2][aRow] = av0.z; As[aK8 + 3][aRow] = av0.w;
        As[aK8 + 4][aRow] = av1.x; As[aK8 + 5][aRow] = av1.y;
        As[aK8 + 6][aRow] = av1.z; As[aK8 + 7][aRow] = av1.w;
        Bs[aK8 + 0][aRow] = bv0.x; Bs[aK8 + 1][aRow] = bv0.y;
        Bs[aK8 + 2][aRow] = bv0.z; Bs[aK8 + 3][aRow] = bv0.w;
        Bs[aK8 + 4][aRow] = bv1.x; Bs[aK8 + 5][aRow] = bv1.y;
        Bs[aK8 + 6][aRow] = bv1.z; Bs[aK8 + 7][aRow] = bv1.w;
        __syncthreads();

        #pragma unroll
        for (int k = 0; k < 16; k++) {
            float a[8];
            *(float4*)(&a[0]) = *(const float4*)(&As[k][ty * 8]);
            *(float4*)(&a[4]) = *(const float4*)(&As[k][ty * 8 + 4]);
            ulonglong2 bq0 = *(const ulonglong2*)(&Bs[k][tx * 8]);
            ulonglong2 bq1 = *(const ulonglong2*)(&Bs[k][tx * 8 + 4]);
            unsigned long long b2[4] = {bq0.x, bq0.y, bq1.x, bq1.y};
            #pragma unroll
            for (int i = 0; i < 8; i++) {
                const unsigned long long a2 = pack2(a[i], a[i]);
                fma2(acc2[i][0], a2, b2[0]);
                fma2(acc2[i][1], a2, b2[1]);
                fma2(acc2[i][2], a2, b2[2]);
                fma2(acc2[i][3], a2, b2[3]);
            }
        }
    }

    // Epilogue: bias + (optional) [S,B] -> [B,S] row permutation
    float bb[8];
    #pragma unroll
    for (int jx = 0; jx < 8; jx++) {
        const int cn = col0 + tx * 8 + jx;
        float bvv = bias1 ? bias1[cn] : 0.0f;
        if (bias2) bvv += bias2[cn];
        bb[jx] = bvv;
    }
    #pragma unroll
    for (int i = 0; i < 8; i++) {
        const int r = row0 + ty * 8 + i;
        size_t base;
        if (permuteOut) {
            const int bidx = r & (Bn - 1);
            const int tt   = r >> 6;
            base = ((size_t)bidx * Sn + tt) * (size_t)N;
        } else {
            base = (size_t)r * (size_t)N;
        }
        const float2 c0 = unpack2(acc2[i][0]);
        const float2 c1 = unpack2(acc2[i][1]);
        const float2 c2 = unpack2(acc2[i][2]);
        const float2 c3 = unpack2(acc2[i][3]);
        float4 v0, v1;
        v0.x = c0.x + bb[0]; v0.y = c0.y + bb[1];
        v0.z = c1.x + bb[2]; v0.w = c1.y + bb[3];
        v1.x = c2.x + bb[4]; v1.y = c2.y + bb[5];
        v1.z = c3.x + bb[6]; v1.w = c3.y + bb[7];
        *(float4*)(C + base + col0 + tx * 8)     = v0;
        *(float4*)(C + base + col0 + tx * 8 + 4) = v1;
    }
}

// ---------------------------------------------------------------------------
// Launch: 5 graph nodes. Output layout: logits[B,S,V], h0[B,H], h1[B,H].
// ---------------------------------------------------------------------------
extern "C" void kernel_launch(void* const* d_in, const int* in_sizes, int n_in,
                              void* d_out, int out_size) {
    const int*   x    = (const int*)  d_in[0];
    const float* emb  = (const float*)d_in[1];
    const float* Wxh0 = (const float*)d_in[2];
    const float* bxh0 = (const float*)d_in[3];
    const float* Whh0 = (const float*)d_in[4];
    const float* bhh0 = (const float*)d_in[5];
    const float* Wxh1 = (const float*)d_in[6];
    const float* bxh1 = (const float*)d_in[7];
    const float* Whh1 = (const float*)d_in[8];
    const float* bhh1 = (const float*)d_in[9];
    const float* Wout = (const float*)d_in[10];
    const float* bout = (const float*)d_in[11];
    float* out = (float*)d_out;

    void* p;
    cudaGetSymbolAddress(&p, g_seq0); float* seq0 = (float*)p;
    cudaGetSymbolAddress(&p, g_A1);   float* A1   = (float*)p;
    cudaGetSymbolAddress(&p, g_T);    float* Tt   = (float*)p;

    cudaFuncSetAttribute(rnn_scan,
                         cudaFuncAttributeMaxDynamicSharedMemorySize,
                         SCAN_SMEM);

    const size_t logitsElems = (size_t)Bn * Sn * Vn;
    float* hf0 = out + logitsElems;
    float* hf1 = out + logitsElems + (size_t)Bn * Hn;

    // 1) Fused embedding + input-projection table
    build_table<<<Vn, 256>>>(emb, Wxh0, bxh0, bhh0);

    // 2) Layer-0 scan (8-CTA clusters, DSMEM h-exchange)
    rnn_scan<<<SCAN_CTAS, 256, SCAN_SMEM>>>(Whh0, 0, x, Tt, nullptr,
                                            seq0, hf0);

    // 3) A1 = seq0 @ Wxh1^T + bxh1 + bhh1   ([S*B, 512] x [512,512]^T)
    {
        dim3 grid(Hn / 128, (Bn * Sn) / 128);
        sgemm_bt<<<grid, 256>>>(seq0, Wxh1, bxh1, bhh1, A1,
                                Bn * Sn, Hn, Hn, 0);
    }

    // 4) Layer-1 scan (overwrites seq0 with h1 sequence)
    rnn_scan<<<SCAN_CTAS, 256, SCAN_SMEM>>>(Whh1, 1, x, Tt, A1,
                                            seq0, hf1);

    // 5) logits = seq1 @ Wout^T + bout, written permuted to [B,S,V]
    {
        dim3 grid(Vn / 128, (Bn * Sn) / 128);
        sgemm_bt<<<grid, 256>>>(seq0, Wout, bout, nullptr, out,
                                Bn * Sn, Vn, Hn, 1);
    }
}

// round 14
// speedup vs baseline: 3.4799x; 3.4799x over previous
#include <cuda_runtime.h>
#include <math.h>

// ---------------------------------------------------------------------------
// Problem dims (fixed by dataset): V=1024, E=256, H=512, B=64, S=2048
// ---------------------------------------------------------------------------
constexpr int Sn = 2048;
constexpr int Bn = 64;
constexpr int Hn = 512;
constexpr int En = 256;
constexpr int Vn = 1024;

constexpr int SCAN_CTAS = 128;                 // 8 b-groups x 16 j-groups
constexpr int SEQ_ELEMS = Sn * Bn * Hn;        // 67,108,864 floats (256 MB)
constexpr int SCAN_SMEM = (32 * 516 + 8 * 516) * 4;   // 82,560 B

// Device-global scratch (allocation-free per harness rules)
__device__ float        g_T[Vn * Hn];          // emb @ Wxh0^T + bxh0 + bhh0
__device__ float        g_seq0[SEQ_ELEMS];     // h0 sequence, reused as h1 seq
__device__ float        g_A1[SEQ_ELEMS];       // layer-1 precomputed input term
__device__ float        g_hping[2 * Bn * Hn];  // ping-pong hidden state
__device__ unsigned int g_bars[8 * 32];        // per-group ctr, 128B padded

// ---------------------------------------------------------------------------
// Packed fp32x2 FMA helpers (gemm inner loop)
// ---------------------------------------------------------------------------
__device__ __forceinline__ void fma2(unsigned long long& d,
                                     unsigned long long a,
                                     unsigned long long b) {
    asm("fma.rn.f32x2 %0, %1, %2, %0;" : "+l"(d) : "l"(a), "l"(b));
}
__device__ __forceinline__ unsigned long long pack2(float lo, float hi) {
    unsigned long long r;
    asm("mov.b64 %0, {%1, %2};" : "=l"(r) : "f"(lo), "f"(hi));
    return r;
}
__device__ __forceinline__ float2 unpack2(unsigned long long v) {
    float2 r;
    asm("mov.b64 {%0, %1}, %2;" : "=f"(r.x), "=f"(r.y) : "l"(v));
    return r;
}

// Release-arrive / acquire-poll grid barrier primitives (CG-style)
__device__ __forceinline__ void bar_arrive_release(unsigned int* ctr) {
    unsigned old;
    asm volatile("atom.release.gpu.global.add.u32 %0, [%1], 1;"
                 : "=r"(old) : "l"(ctr) : "memory");
}
__device__ __forceinline__ unsigned bar_load_acquire(unsigned int* ctr) {
    unsigned v;
    asm volatile("ld.acquire.gpu.global.u32 %0, [%1];"
                 : "=r"(v) : "l"(ctr) : "memory");
    return v;
}

// ---------------------------------------------------------------------------
// Init: reset barrier counters + zero hidden-state ping-pong (every replay)
// ---------------------------------------------------------------------------
__global__ void scan_init() {
    unsigned i = blockIdx.x * blockDim.x + threadIdx.x;
    if (i < 8 * 32) g_bars[i] = 0u;
    for (unsigned k = i; k < 2u * Bn * Hn; k += gridDim.x * blockDim.x)
        g_hping[k] = 0.0f;
}

// ---------------------------------------------------------------------------
// T[v][j] = sum_e emb[v][e] * Wxh0[j][e] + bxh0[j] + bhh0[j]
// ---------------------------------------------------------------------------
__global__ void __launch_bounds__(256) build_table(
    const float* __restrict__ emb, const float* __restrict__ Wxh0,
    const float* __restrict__ bxh0, const float* __restrict__ bhh0)
{
    __shared__ float es[En];
    const int v = blockIdx.x;
    const int tid = threadIdx.x;
    es[tid] = emb[(size_t)v * En + tid];
    __syncthreads();
    #pragma unroll
    for (int jj = 0; jj < 2; jj++) {
        const int j = tid + jj * 256;
        const float4* w = (const float4*)(Wxh0 + (size_t)j * En);
        float s = 0.0f;
        #pragma unroll 16
        for (int k = 0; k < En / 4; k++) {
            float4 wv = __ldg(&w[k]);
            s = fmaf(wv.x, es[4 * k + 0], s);
            s = fmaf(wv.y, es[4 * k + 1], s);
            s = fmaf(wv.z, es[4 * k + 2], s);
            s = fmaf(wv.w, es[4 * k + 3], s);
        }
        g_T[(size_t)v * Hn + j] = s + bxh0[j] + bhh0[j];
    }
}

// ---------------------------------------------------------------------------
// Persistent recurrent scan, register-tiled core.
// CTA c: batch group grp=(c&7) -> rows b0=grp*8; j-group (c>>3) -> j0*32.
// 32 Whh rows resident in smem; 8 h rows staged per step (16 KB from L2).
// Thread map: warp w, half hh=l>>4 -> tile = w*2+hh of 16 tiles (4b x 4j);
// lane kt=l&15 owns K-slice {kt*4 + m*64 + 0..3, m=0..7} (32 of 512 k).
// Each thread: 4 h-float4 + 4 w-float4 loads per chunk -> 64 FMAs
// (2 B delivered smem per FMA; ~2048 LDS-cyc/step vs 8192 before).
// Partials reduced via 4-round shfl butterfly over the 16 kt lanes.
// Per-group 16-CTA barrier: release-arrive / acquire-poll.
// ---------------------------------------------------------------------------
__global__ void __launch_bounds__(256, 1) rnn_scan(
    const float* __restrict__ Whh,     // [512][512] (out j, in k)
    int mode,
    const int*   __restrict__ x,       // [B][S]      (mode 0)
    const float* __restrict__ T,       // [V][H]      (mode 0)
    const float* __restrict__ A1,      // [S][B][H]   (mode 1)
    float* __restrict__ hseq,          // [S][B][H]
    float* __restrict__ hfinal)        // [B][H]
{
    extern __shared__ float sm[];
    float* Ws = sm;                    // [32][516] padded (pitch 129 float4)
    float* hs = sm + 32 * 516;         // [8][516]  padded

    const int c    = blockIdx.x;
    const int grp  = c & 7;
    const int b0   = grp * 8;
    const int j0   = (c >> 3) * 32;
    const int tid  = threadIdx.x;
    const int w    = tid >> 5;
    const int l    = tid & 31;
    const int kt   = l & 15;                 // K-slice id
    const int tile = w * 2 + (l >> 4);       // 0..15
    const int bi0  = (tile >> 3) * 4;        // 0 or 4
    const int jj0  = (tile & 7) * 4;         // 0..28
    // Output this lane writes after reduction: idx = kt
    const int obi  = bi0 + (kt >> 2);
    const int ojj  = jj0 + (kt & 3);
    const int ob   = b0 + obi;
    const int oj   = j0 + ojj;
    unsigned int* ctr = &g_bars[grp * 32];

    // Load this CTA's 32 Whh rows once (resident for all 2048 steps)
    for (int i = tid; i < 32 * Hn; i += 256) {
        const int r = i >> 9;
        const int k = i & 511;
        Ws[r * 516 + k] = Whh[(size_t)(j0 + r) * Hn + k];
    }

    const float4* ws4 = (const float4*)Ws;
    const float4* hs4 = (const float4*)hs;

    for (int t = 0; t < Sn; t++) {
        // Input term for this lane's output (independent of h staging)
        float base;
        if (mode == 0) {
            const int xv = x[(size_t)ob * Sn + t];
            base = __ldg(&T[(size_t)xv * Hn + oj]);
        } else {
            base = __ldcs(&A1[((size_t)t * Bn + ob) * Hn + oj]);
        }

        // Stage this group's 8 h rows (16 KB) into smem, L2-fresh
        const float* hsrc = g_hping + (size_t)(t & 1) * (Bn * Hn)
                                    + (size_t)b0 * Hn;
        #pragma unroll
        for (int q = 0; q < 4; q++) {
            const int i   = tid + q * 256;        // 0..1023 float4 slots
            const int row = i >> 7;               // 128 float4 per row
            const int c4  = (i & 127) << 2;
            float4 v = __ldcg((const float4*)(hsrc + row * Hn + c4));
            *(float4*)(hs + row * 516 + c4) = v;
        }
        __syncthreads();   // hs (and, at t=0, Ws) ready

        // 4b x 4j x (32 k) partial tile
        float acc[16] = {0.f, 0.f, 0.f, 0.f, 0.f, 0.f, 0.f, 0.f,
                         0.f, 0.f, 0.f, 0.f, 0.f, 0.f, 0.f, 0.f};
        #pragma unroll
        for (int m = 0; m < 8; m++) {
            const int kq = kt + m * 16;           // float4 index within row
            float4 hv0 = hs4[(bi0 + 0) * 129 + kq];
            float4 hv1 = hs4[(bi0 + 1) * 129 + kq];
            float4 hv2 = hs4[(bi0 + 2) * 129 + kq];
            float4 hv3 = hs4[(bi0 + 3) * 129 + kq];
            float4 wv0 = ws4[(jj0 + 0) * 129 + kq];
            float4 wv1 = ws4[(jj0 + 1) * 129 + kq];
            float4 wv2 = ws4[(jj0 + 2) * 129 + kq];
            float4 wv3 = ws4[(jj0 + 3) * 129 + kq];
            #pragma unroll
            for (int i = 0; i < 4; i++) {
                const float4 hv = (i == 0) ? hv0 : (i == 1) ? hv1
                                 : (i == 2) ? hv2 : hv3;
                #pragma unroll
                for (int jx = 0; jx < 4; jx++) {
                    const float4 wv = (jx == 0) ? wv0 : (jx == 1) ? wv1
                                     : (jx == 2) ? wv2 : wv3;
                    float s = acc[i * 4 + jx];
                    s = fmaf(hv.x, wv.x, s);
                    s = fmaf(hv.y, wv.y, s);
                    s = fmaf(hv.z, wv.z, s);
                    s = fmaf(hv.w, wv.w, s);
                    acc[i * 4 + jx] = s;
                }
            }
        }

        // Reduce over the 16 kt lanes (butterfly, width 16)
        #pragma unroll
        for (int d = 8; d >= 1; d >>= 1) {
            #pragma unroll
            for (int q = 0; q < 16; q++)
                acc[q] += __shfl_xor_sync(0xffffffffu, acc[q], d, 16);
        }

        // Lane kt writes output #kt of its tile
        const float y = tanhf(acc[kt] + base);
        g_hping[(size_t)((t + 1) & 1) * (Bn * Hn) + (size_t)ob * Hn + oj] = y;
        hseq[((size_t)t * Bn + ob) * Hn + oj] = y;
        if (t == Sn - 1) hfinal[(size_t)ob * Hn + oj] = y;

        // Per-group 16-CTA barrier (release-arrive / acquire-poll)
        __syncthreads();                 // all CTA stores happen-before tid0
        if (tid == 0) {
            bar_arrive_release(ctr);     // publishes this CTA's y writes
            const unsigned target = (unsigned)(t + 1) * 16u;
            while (bar_load_acquire(ctr) < target) { }
        }
        __syncthreads();                 // release CTA; guards hs reuse
    }
}

// ---------------------------------------------------------------------------
// SGEMM: C[M,N] = A[M,K] @ B[N,K]^T + bias1[n] (+ bias2[n])
// 128x128 tile, BK=16, 256 threads, 8x8 microtile via FFMA2, 2 blocks/SM.
// permuteOut: remap row r (= t*B + b) -> out row b*S + t  (logits layout).
// ---------------------------------------------------------------------------
__global__ void __launch_bounds__(256, 2) sgemm_bt(
    const float* __restrict__ A, const float* __restrict__ Bm,
    const float* __restrict__ bias1, const float* __restrict__ bias2,
    float* __restrict__ C, int M, int N, int K, int permuteOut)
{
    __shared__ float As[16][128];
    __shared__ float Bs[16][128];

    const int tid  = threadIdx.x;
    const int tx   = tid & 15;          // 0..15 -> 8 cols each
    const int ty   = tid >> 4;          // 0..15 -> 8 rows each
    const int row0 = blockIdx.y * 128;
    const int col0 = blockIdx.x * 128;

    const int aRow = tid >> 1;          // 0..127
    const int aK8  = (tid & 1) * 8;     // 0 or 8
    const float* Ag = A  + (size_t)(row0 + aRow) * K + aK8;
    const float* Bg = Bm + (size_t)(col0 + aRow) * K + aK8;

    unsigned long long acc2[8][4] = {};  // 8 rows x 4 packed col-pairs

    for (int k0 = 0; k0 < K; k0 += 16) {
        const float4 av0 = __ldg((const float4*)(Ag + k0));
        const float4 av1 = __ldg((const float4*)(Ag + k0 + 4));
        const float4 bv0 = __ldg((const float4*)(Bg + k0));
        const float4 bv1 = __ldg((const float4*)(Bg + k0 + 4));
        __syncthreads();                // previous tile fully consumed
        As[aK8 + 0][aRow] = av0.x; As[aK8 + 1][aRow] = av0.y;
        As[aK8 + 2][aRow] = av0.z; As[aK8 + 3][aRow] = av0.w;
        As[aK8 + 4][aRow] = av1.x; As[aK8 + 5][aRow] = av1.y;
        As[aK8 + 6][aRow] = av1.z; As[aK8 + 7][aRow] = av1.w;
        Bs[aK8 + 0][aRow] = bv0.x; Bs[aK8 + 1][aRow] = bv0.y;
        Bs[aK8 + 2][aRow] = bv0.z; Bs[aK8 + 3][aRow] = bv0.w;
        Bs[aK8 + 4][aRow] = bv1.x; Bs[aK8 + 5][aRow] = bv1.y;
        Bs[aK8 + 6][aRow] = bv1.z; Bs[aK8 + 7][aRow] = bv1.w;
        __syncthreads();

        #pragma unroll
        for (int k = 0; k < 16; k++) {
            float a[8];
            *(float4*)(&a[0]) = *(const float4*)(&As[k][ty * 8]);
            *(float4*)(&a[4]) = *(const float4*)(&As[k][ty * 8 + 4]);
            ulonglong2 bq0 = *(const ulonglong2*)(&Bs[k][tx * 8]);
            ulonglong2 bq1 = *(const ulonglong2*)(&Bs[k][tx * 8 + 4]);
            unsigned long long b2[4] = {bq0.x, bq0.y, bq1.x, bq1.y};
            #pragma unroll
            for (int i = 0; i < 8; i++) {
                const unsigned long long a2 = pack2(a[i], a[i]);
                fma2(acc2[i][0], a2, b2[0]);
                fma2(acc2[i][1], a2, b2[1]);
                fma2(acc2[i][2], a2, b2[2]);
                fma2(acc2[i][3], a2, b2[3]);
            }
        }
    }

    // Epilogue: bias + (optional) [S,B] -> [B,S] row permutation
    float bb[8];
    #pragma unroll
    for (int jx = 0; jx < 8; jx++) {
        const int cn = col0 + tx * 8 + jx;
        float bvv = bias1 ? bias1[cn] : 0.0f;
        if (bias2) bvv += bias2[cn];
        bb[jx] = bvv;
    }
    #pragma unroll
    for (int i = 0; i < 8; i++) {
        const int r = row0 + ty * 8 + i;
        size_t base;
        if (permuteOut) {
            const int bidx = r & (Bn - 1);
            const int tt   = r >> 6;
            base = ((size_t)bidx * Sn + tt) * (size_t)N;
        } else {
            base = (size_t)r * (size_t)N;
        }
        const float2 c0 = unpack2(acc2[i][0]);
        const float2 c1 = unpack2(acc2[i][1]);
        const float2 c2 = unpack2(acc2[i][2]);
        const float2 c3 = unpack2(acc2[i][3]);
        float4 v0, v1;
        v0.x = c0.x + bb[0]; v0.y = c0.y + bb[1];
        v0.z = c1.x + bb[2]; v0.w = c1.y + bb[3];
        v1.x = c2.x + bb[4]; v1.y = c2.y + bb[5];
        v1.z = c3.x + bb[6]; v1.w = c3.y + bb[7];
        *(float4*)(C + base + col0 + tx * 8)     = v0;
        *(float4*)(C + base + col0 + tx * 8 + 4) = v1;
    }
}

// ---------------------------------------------------------------------------
// Launch: 7 graph nodes. Output layout: logits[B,S,V], h0[B,H], h1[B,H].
// ---------------------------------------------------------------------------
extern "C" void kernel_launch(void* const* d_in, const int* in_sizes, int n_in,
                              void* d_out, int out_size) {
    const int*   x    = (const int*)  d_in[0];
    const float* emb  = (const float*)d_in[1];
    const float* Wxh0 = (const float*)d_in[2];
    const float* bxh0 = (const float*)d_in[3];
    const float* Whh0 = (const float*)d_in[4];
    const float* bhh0 = (const float*)d_in[5];
    const float* Wxh1 = (const float*)d_in[6];
    const float* bxh1 = (const float*)d_in[7];
    const float* Whh1 = (const float*)d_in[8];
    const float* bhh1 = (const float*)d_in[9];
    const float* Wout = (const float*)d_in[10];
    const float* bout = (const float*)d_in[11];
    float* out = (float*)d_out;

    void* p;
    cudaGetSymbolAddress(&p, g_seq0); float* seq0 = (float*)p;
    cudaGetSymbolAddress(&p, g_A1);   float* A1   = (float*)p;
    cudaGetSymbolAddress(&p, g_T);    float* Tt   = (float*)p;

    cudaFuncSetAttribute(rnn_scan,
                         cudaFuncAttributeMaxDynamicSharedMemorySize,
                         SCAN_SMEM);

    const size_t logitsElems = (size_t)Bn * Sn * Vn;
    float* hf0 = out + logitsElems;
    float* hf1 = out + logitsElems + (size_t)Bn * Hn;

    // 1) Fused embedding + input-projection table
    build_table<<<Vn, 256>>>(emb, Wxh0, bxh0, bhh0);

    // 2) Layer-0 scan
    scan_init<<<64, 256>>>();
    rnn_scan<<<SCAN_CTAS, 256, SCAN_SMEM>>>(Whh0, 0, x, Tt, nullptr,
                                            seq0, hf0);

    // 3) A1 = seq0 @ Wxh1^T + bxh1 + bhh1   ([S*B, 512] x [512,512]^T)
    {
        dim3 grid(Hn / 128, (Bn * Sn) / 128);
        sgemm_bt<<<grid, 256>>>(seq0, Wxh1, bxh1, bhh1, A1,
                                Bn * Sn, Hn, Hn, 0);
    }

    // 4) Layer-1 scan (overwrites seq0 with h1 sequence)
    scan_init<<<64, 256>>>();
    rnn_scan<<<SCAN_CTAS, 256, SCAN_SMEM>>>(Whh1, 1, x, Tt, A1,
                                            seq0, hf1);

    // 5) logits = seq1 @ Wout^T + bout, written permuted to [B,S,V]
    {
        dim3 grid(Vn / 128, (Bn * Sn) / 128);
        sgemm_bt<<<grid, 256>>>(seq0, Wout, bout, nullptr, out,
                                Bn * Sn, Vn, Hn, 1);
    }
}

// round 15
// speedup vs baseline: 4.0825x; 1.1732x over previous
#include <cuda_runtime.h>
#include <cuda_bf16.h>
#include <math.h>

// ---------------------------------------------------------------------------
// Problem dims (fixed by dataset): V=1024, E=256, H=512, B=64, S=2048
// ---------------------------------------------------------------------------
constexpr int Sn = 2048;
constexpr int Bn = 64;
constexpr int Hn = 512;
constexpr int En = 256;
constexpr int Vn = 1024;

constexpr int SCAN_CTAS = 128;                 // 8 b-groups x 16 j-groups
constexpr int SEQ_ELEMS = Sn * Bn * Hn;        // 67,108,864
constexpr int SCAN_SMEM = (32 * 516 + 8 * 516) * 4;   // 82,560 B

// Device-global scratch (allocation-free per harness rules)
__device__ float          g_T[Vn * Hn];        // emb @ Wxh0^T + bxh0 + bhh0
__device__ float          g_A1[SEQ_ELEMS];     // layer-1 input term (fp32)
__device__ __nv_bfloat16  g_seqhi[SEQ_ELEMS];  // h sequence, bf16 hi part
__device__ __nv_bfloat16  g_seqlo[SEQ_ELEMS];  // h sequence, bf16 lo part
__device__ __nv_bfloat16  g_W1hi[Hn * Hn], g_W1lo[Hn * Hn];
__device__ __nv_bfloat16  g_Wohi[Vn * Hn], g_Wolo[Vn * Hn];
__device__ float          g_hping[2 * Bn * Hn];
__device__ unsigned int   g_bars[8 * 32];      // per-group ctr, 128B padded

// ---------------------------------------------------------------------------
// Packed fp32x2 FMA helpers (scan inner loop)
// ---------------------------------------------------------------------------
__device__ __forceinline__ void fma2(unsigned long long& d,
                                     unsigned long long a,
                                     unsigned long long b) {
    asm("fma.rn.f32x2 %0, %1, %2, %0;" : "+l"(d) : "l"(a), "l"(b));
}
__device__ __forceinline__ float2 unpack2(unsigned long long v) {
    float2 r;
    asm("mov.b64 {%0, %1}, %2;" : "=f"(r.x), "=f"(r.y) : "l"(v));
    return r;
}

// Release-arrive / acquire-poll grid barrier primitives
__device__ __forceinline__ void bar_arrive_release(unsigned int* ctr) {
    unsigned old;
    asm volatile("atom.release.gpu.global.add.u32 %0, [%1], 1;"
                 : "=r"(old) : "l"(ctr) : "memory");
}
__device__ __forceinline__ unsigned bar_load_acquire(unsigned int* ctr) {
    unsigned v;
    asm volatile("ld.acquire.gpu.global.u32 %0, [%1];"
                 : "=r"(v) : "l"(ctr) : "memory");
    return v;
}

// bf16 mma: D(f32) += A(bf16 16x16) * B(bf16 16x8)   [sm_80 PTX, ok on sm_103]
__device__ __forceinline__ void mma_bf16(float* d, const unsigned* a,
                                         const unsigned* b) {
    asm volatile(
        "mma.sync.aligned.m16n8k16.row.col.f32.bf16.bf16.f32 "
        "{%0,%1,%2,%3}, {%4,%5,%6,%7}, {%8,%9}, {%0,%1,%2,%3};"
        : "+f"(d[0]), "+f"(d[1]), "+f"(d[2]), "+f"(d[3])
        : "r"(a[0]), "r"(a[1]), "r"(a[2]), "r"(a[3]),
          "r"(b[0]), "r"(b[1]));
}

// ---------------------------------------------------------------------------
// Init: reset barrier counters + zero hidden-state ping-pong (every replay)
// ---------------------------------------------------------------------------
__global__ void scan_init() {
    unsigned i = blockIdx.x * blockDim.x + threadIdx.x;
    if (i < 8 * 32) g_bars[i] = 0u;
    for (unsigned k = i; k < 2u * Bn * Hn; k += gridDim.x * blockDim.x)
        g_hping[k] = 0.0f;
}

// Split fp32 -> (hi, lo) bf16 pair (weights prep)
__global__ void split_fp32(const float* __restrict__ src,
                           __nv_bfloat16* __restrict__ hi,
                           __nv_bfloat16* __restrict__ lo, int n) {
    const int i = blockIdx.x * 256 + threadIdx.x;
    if (i < n) {
        const float v = src[i];
        const __nv_bfloat16 h = __float2bfloat16_rn(v);
        hi[i] = h;
        lo[i] = __float2bfloat16_rn(v - __bfloat162float(h));
    }
}

// ---------------------------------------------------------------------------
// T[v][j] = sum_e emb[v][e] * Wxh0[j][e] + bxh0[j] + bhh0[j]
// ---------------------------------------------------------------------------
__global__ void __launch_bounds__(256) build_table(
    const float* __restrict__ emb, const float* __restrict__ Wxh0,
    const float* __restrict__ bxh0, const float* __restrict__ bhh0)
{
    __shared__ float es[En];
    const int v = blockIdx.x;
    const int tid = threadIdx.x;
    es[tid] = emb[(size_t)v * En + tid];
    __syncthreads();
    #pragma unroll
    for (int jj = 0; jj < 2; jj++) {
        const int j = tid + jj * 256;
        const float4* w = (const float4*)(Wxh0 + (size_t)j * En);
        float s = 0.0f;
        #pragma unroll 16
        for (int k = 0; k < En / 4; k++) {
            float4 wv = __ldg(&w[k]);
            s = fmaf(wv.x, es[4 * k + 0], s);
            s = fmaf(wv.y, es[4 * k + 1], s);
            s = fmaf(wv.z, es[4 * k + 2], s);
            s = fmaf(wv.w, es[4 * k + 3], s);
        }
        g_T[(size_t)v * Hn + j] = s + bxh0[j] + bhh0[j];
    }
}

// ---------------------------------------------------------------------------
// Persistent recurrent scan, register-tiled core (see R14).
// Changes: 15-shfl recursive-halving reduction; emits bf16 hi/lo sequence.
// ---------------------------------------------------------------------------
__global__ void __launch_bounds__(256, 1) rnn_scan(
    const float* __restrict__ Whh,
    int mode,
    const int*   __restrict__ x,
    const float* __restrict__ T,
    const float* __restrict__ A1,
    __nv_bfloat16* __restrict__ seqhi,
    __nv_bfloat16* __restrict__ seqlo,
    float* __restrict__ hfinal)
{
    extern __shared__ float sm[];
    float* Ws = sm;                    // [32][516]
    float* hs = sm + 32 * 516;         // [8][516]

    const int c    = blockIdx.x;
    const int grp  = c & 7;
    const int b0   = grp * 8;
    const int j0   = (c >> 3) * 32;
    const int tid  = threadIdx.x;
    const int w    = tid >> 5;
    const int l    = tid & 31;
    const int kt   = l & 15;
    const int tile = w * 2 + (l >> 4);
    const int bi0  = (tile >> 3) * 4;
    const int jj0  = (tile & 7) * 4;
    const int obi  = bi0 + (kt >> 2);
    const int ojj  = jj0 + (kt & 3);
    const int ob   = b0 + obi;
    const int oj   = j0 + ojj;
    unsigned int* ctr = &g_bars[grp * 32];

    for (int i = tid; i < 32 * Hn; i += 256) {
        const int r = i >> 9;
        const int k = i & 511;
        Ws[r * 516 + k] = Whh[(size_t)(j0 + r) * Hn + k];
    }

    const float4* ws4 = (const float4*)Ws;
    const float4* hs4 = (const float4*)hs;

    for (int t = 0; t < Sn; t++) {
        float base;
        if (mode == 0) {
            const int xv = x[(size_t)ob * Sn + t];
            base = __ldg(&T[(size_t)xv * Hn + oj]);
        } else {
            base = __ldcs(&A1[((size_t)t * Bn + ob) * Hn + oj]);
        }

        const float* hsrc = g_hping + (size_t)(t & 1) * (Bn * Hn)
                                    + (size_t)b0 * Hn;
        #pragma unroll
        for (int q = 0; q < 4; q++) {
            const int i   = tid + q * 256;
            const int row = i >> 7;
            const int c4  = (i & 127) << 2;
            float4 v = __ldcg((const float4*)(hsrc + row * Hn + c4));
            *(float4*)(hs + row * 516 + c4) = v;
        }
        __syncthreads();

        float acc[16] = {0.f, 0.f, 0.f, 0.f, 0.f, 0.f, 0.f, 0.f,
                         0.f, 0.f, 0.f, 0.f, 0.f, 0.f, 0.f, 0.f};
        #pragma unroll
        for (int m = 0; m < 8; m++) {
            const int kq = kt + m * 16;
            float4 hv0 = hs4[(bi0 + 0) * 129 + kq];
            float4 hv1 = hs4[(bi0 + 1) * 129 + kq];
            float4 hv2 = hs4[(bi0 + 2) * 129 + kq];
            float4 hv3 = hs4[(bi0 + 3) * 129 + kq];
            float4 wv0 = ws4[(jj0 + 0) * 129 + kq];
            float4 wv1 = ws4[(jj0 + 1) * 129 + kq];
            float4 wv2 = ws4[(jj0 + 2) * 129 + kq];
            float4 wv3 = ws4[(jj0 + 3) * 129 + kq];
            #pragma unroll
            for (int i = 0; i < 4; i++) {
                const float4 hv = (i == 0) ? hv0 : (i == 1) ? hv1
                                 : (i == 2) ? hv2 : hv3;
                #pragma unroll
                for (int jx = 0; jx < 4; jx++) {
                    const float4 wv = (jx == 0) ? wv0 : (jx == 1) ? wv1
                                     : (jx == 2) ? wv2 : wv3;
                    float s = acc[i * 4 + jx];
                    s = fmaf(hv.x, wv.x, s);
                    s = fmaf(hv.y, wv.y, s);
                    s = fmaf(hv.z, wv.z, s);
                    s = fmaf(hv.w, wv.w, s);
                    acc[i * 4 + jx] = s;
                }
            }
        }

        // Recursive-halving reduction over the 16 kt lanes: 15 shfl total.
        // After round d, lane keeps the half matching its kt bit; payload
        // halves each round. Final acc[0] = full sum for output index kt.
        {
            const bool u8 = (kt & 8);
            #pragma unroll
            for (int i = 0; i < 8; i++) {
                float kept = u8 ? acc[i + 8] : acc[i];
                float sent = u8 ? acc[i] : acc[i + 8];
                acc[i] = kept + __shfl_xor_sync(0xffffffffu, sent, 8, 16);
            }
            const bool u4 = (kt & 4);
            #pragma unroll
            for (int i = 0; i < 4; i++) {
                float kept = u4 ? acc[i + 4] : acc[i];
                float sent = u4 ? acc[i] : acc[i + 4];
                acc[i] = kept + __shfl_xor_sync(0xffffffffu, sent, 4, 16);
            }
            const bool u2 = (kt & 2);
            #pragma unroll
            for (int i = 0; i < 2; i++) {
                float kept = u2 ? acc[i + 2] : acc[i];
                float sent = u2 ? acc[i] : acc[i + 2];
                acc[i] = kept + __shfl_xor_sync(0xffffffffu, sent, 2, 16);
            }
            const bool u1 = (kt & 1);
            {
                float kept = u1 ? acc[1] : acc[0];
                float sent = u1 ? acc[0] : acc[1];
                acc[0] = kept + __shfl_xor_sync(0xffffffffu, sent, 1, 16);
            }
        }

        const float y = tanhf(acc[0] + base);
        g_hping[(size_t)((t + 1) & 1) * (Bn * Hn) + (size_t)ob * Hn + oj] = y;

        const size_t idx = ((size_t)t * Bn + ob) * Hn + oj;
        const __nv_bfloat16 yh = __float2bfloat16_rn(y);
        seqhi[idx] = yh;
        seqlo[idx] = __float2bfloat16_rn(y - __bfloat162float(yh));
        if (t == Sn - 1) hfinal[(size_t)ob * Hn + oj] = y;

        __syncthreads();
        if (tid == 0) {
            bar_arrive_release(ctr);
            const unsigned target = (unsigned)(t + 1) * 16u;
            while (bar_load_acquire(ctr) < target) { }
        }
        __syncthreads();
    }
}

// ---------------------------------------------------------------------------
// Split-bf16 tensor-core GEMM via mma.sync.m16n8k16:
//   C[M,N] = A[M,K] @ B[N,K]^T + bias1 (+bias2),
//   A,B given as (hi,lo) bf16 pairs; D += Ahi*Bhi + Ahi*Blo + Alo*Bhi.
// 128x128 tile, BK=32, 256 threads (8 warps as 2m x 4n, each 64x32).
// smem pitch 40 halves (80 B) -> conflict-free LDS.32 fragment loads.
// permuteOut: row r (= t*B + b) -> out row b*S + t.
// ---------------------------------------------------------------------------
constexpr int GP = 40;   // smem row pitch in bf16 halves

__global__ void __launch_bounds__(256) gemm_mma(
    const __nv_bfloat16* __restrict__ Ahi_g,
    const __nv_bfloat16* __restrict__ Alo_g,
    const __nv_bfloat16* __restrict__ Bhi_g,
    const __nv_bfloat16* __restrict__ Blo_g,
    const float* __restrict__ bias1, const float* __restrict__ bias2,
    float* __restrict__ C, int M, int N, int K, int permuteOut)
{
    __shared__ __align__(16) unsigned short Ah[128 * GP], Al[128 * GP];
    __shared__ __align__(16) unsigned short Bh[128 * GP], Bl[128 * GP];

    const int tid = threadIdx.x;
    const int wid = tid >> 5, l = tid & 31;
    const int wm = wid >> 2, wn = wid & 3;   // 2 m-halves x 4 n-quarters
    const int g  = l >> 2,  tq = l & 3;      // mma group / thread-in-group
    const int row0 = blockIdx.y * 128;
    const int col0 = blockIdx.x * 128;

    const int lr = tid >> 1;                 // 0..127 staging row
    const int ls = (tid & 1) * 2;            // 16B segment 0/2

    float acc[4][4][4] = {};                 // [mi][ni][c0..c3]

    for (int kc = 0; kc < K; kc += 32) {
        __syncthreads();                     // frags of prev chunk consumed
        const size_t abase = (size_t)(row0 + lr) * K + kc;
        const size_t bbase = (size_t)(col0 + lr) * K + kc;
        #pragma unroll
        for (int s2 = 0; s2 < 2; s2++) {
            const int s = ls + s2;
            *(uint4*)&Ah[lr * GP + s * 8] =
                __ldg((const uint4*)(Ahi_g + abase + s * 8));
            *(uint4*)&Al[lr * GP + s * 8] =
                __ldg((const uint4*)(Alo_g + abase + s * 8));
            *(uint4*)&Bh[lr * GP + s * 8] =
                __ldg((const uint4*)(Bhi_g + bbase + s * 8));
            *(uint4*)&Bl[lr * GP + s * 8] =
                __ldg((const uint4*)(Blo_g + bbase + s * 8));
        }
        __syncthreads();

        #pragma unroll
        for (int ks = 0; ks < 32; ks += 16) {
            // B fragments (hi+lo) for 4 n-subtiles
            unsigned bh[4][2], bl[4][2];
            #pragma unroll
            for (int ni = 0; ni < 4; ni++) {
                const int boff = (wn * 32 + ni * 8 + g) * GP + ks + 2 * tq;
                bh[ni][0] = *(const unsigned*)&Bh[boff];
                bh[ni][1] = *(const unsigned*)&Bh[boff + 8];
                bl[ni][0] = *(const unsigned*)&Bl[boff];
                bl[ni][1] = *(const unsigned*)&Bl[boff + 8];
            }
            #pragma unroll
            for (int mi = 0; mi < 4; mi++) {
                const int aoff = (wm * 64 + mi * 16 + g) * GP + ks + 2 * tq;
                unsigned ah[4] = {
                    *(const unsigned*)&Ah[aoff],
                    *(const unsigned*)&Ah[aoff + 8 * GP],
                    *(const unsigned*)&Ah[aoff + 8],
                    *(const unsigned*)&Ah[aoff + 8 * GP + 8] };
                unsigned al[4] = {
                    *(const unsigned*)&Al[aoff],
                    *(const unsigned*)&Al[aoff + 8 * GP],
                    *(const unsigned*)&Al[aoff + 8],
                    *(const unsigned*)&Al[aoff + 8 * GP + 8] };
                #pragma unroll
                for (int ni = 0; ni < 4; ni++) {
                    mma_bf16(acc[mi][ni], ah, bh[ni]);
                    mma_bf16(acc[mi][ni], ah, bl[ni]);
                    mma_bf16(acc[mi][ni], al, bh[ni]);
                }
            }
        }
    }

    // Epilogue: bias + optional [S,B] -> [B,S] row permutation
    #pragma unroll
    for (int mi = 0; mi < 4; mi++) {
        #pragma unroll
        for (int rr = 0; rr < 2; rr++) {
            const int r = row0 + wm * 64 + mi * 16 + g + rr * 8;
            size_t basep;
            if (permuteOut) {
                const int bidx = r & (Bn - 1);
                const int tt   = r >> 6;
                basep = ((size_t)bidx * Sn + tt) * (size_t)N;
            } else {
                basep = (size_t)r * (size_t)N;
            }
            #pragma unroll
            for (int ni = 0; ni < 4; ni++) {
                const int n = col0 + wn * 32 + ni * 8 + 2 * tq;
                float b0v = bias1 ? __ldg(&bias1[n])     : 0.0f;
                float b1v = bias1 ? __ldg(&bias1[n + 1]) : 0.0f;
                if (bias2) {
                    b0v += __ldg(&bias2[n]);
                    b1v += __ldg(&bias2[n + 1]);
                }
                float2 v;
                v.x = acc[mi][ni][rr * 2 + 0] + b0v;
                v.y = acc[mi][ni][rr * 2 + 1] + b1v;
                *(float2*)(C + basep + n) = v;
            }
        }
    }
}

// ---------------------------------------------------------------------------
// Launch: 9 graph nodes. Output layout: logits[B,S,V], h0[B,H], h1[B,H].
// ---------------------------------------------------------------------------
extern "C" void kernel_launch(void* const* d_in, const int* in_sizes, int n_in,
                              void* d_out, int out_size) {
    const int*   x    = (const int*)  d_in[0];
    const float* emb  = (const float*)d_in[1];
    const float* Wxh0 = (const float*)d_in[2];
    const float* bxh0 = (const float*)d_in[3];
    const float* Whh0 = (const float*)d_in[4];
    const float* bhh0 = (const float*)d_in[5];
    const float* Wxh1 = (const float*)d_in[6];
    const float* bxh1 = (const float*)d_in[7];
    const float* Whh1 = (const float*)d_in[8];
    const float* bhh1 = (const float*)d_in[9];
    const float* Wout = (const float*)d_in[10];
    const float* bout = (const float*)d_in[11];
    float* out = (float*)d_out;

    void* p;
    cudaGetSymbolAddress(&p, g_A1);    float* A1 = (float*)p;
    cudaGetSymbolAddress(&p, g_T);     float* Tt = (float*)p;
    cudaGetSymbolAddress(&p, g_seqhi); __nv_bfloat16* shi = (__nv_bfloat16*)p;
    cudaGetSymbolAddress(&p, g_seqlo); __nv_bfloat16* slo = (__nv_bfloat16*)p;
    cudaGetSymbolAddress(&p, g_W1hi);  __nv_bfloat16* w1h = (__nv_bfloat16*)p;
    cudaGetSymbolAddress(&p, g_W1lo);  __nv_bfloat16* w1l = (__nv_bfloat16*)p;
    cudaGetSymbolAddress(&p, g_Wohi);  __nv_bfloat16* woh = (__nv_bfloat16*)p;
    cudaGetSymbolAddress(&p, g_Wolo);  __nv_bfloat16* wol = (__nv_bfloat16*)p;

    cudaFuncSetAttribute(rnn_scan,
                         cudaFuncAttributeMaxDynamicSharedMemorySize,
                         SCAN_SMEM);

    const size_t logitsElems = (size_t)Bn * Sn * Vn;
    float* hf0 = out + logitsElems;
    float* hf1 = out + logitsElems + (size_t)Bn * Hn;
    const int M = Bn * Sn;

    // 1) Fused embedding + input-projection table; weight splits
    build_table<<<Vn, 256>>>(emb, Wxh0, bxh0, bhh0);
    split_fp32<<<(Hn * Hn + 255) / 256, 256>>>(Wxh1, w1h, w1l, Hn * Hn);
    split_fp32<<<(Vn * Hn + 255) / 256, 256>>>(Wout, woh, wol, Vn * Hn);

    // 2) Layer-0 scan -> seq hi/lo
    scan_init<<<64, 256>>>();
    rnn_scan<<<SCAN_CTAS, 256, SCAN_SMEM>>>(Whh0, 0, x, Tt, nullptr,
                                            shi, slo, hf0);

    // 3) A1 = seq0 @ Wxh1^T + bxh1 + bhh1  (tensor-core split-bf16)
    {
        dim3 grid(Hn / 128, M / 128);
        gemm_mma<<<grid, 256>>>(shi, slo, w1h, w1l, bxh1, bhh1, A1,
                                M, Hn, Hn, 0);
    }

    // 4) Layer-1 scan (overwrites seq hi/lo with h1 sequence)
    scan_init<<<64, 256>>>();
    rnn_scan<<<SCAN_CTAS, 256, SCAN_SMEM>>>(Whh1, 1, x, Tt, A1,
                                            shi, slo, hf1);

    // 5) logits = seq1 @ Wout^T + bout, permuted to [B,S,V]
    {
        dim3 grid(Vn / 128, M / 128);
        gemm_mma<<<grid, 256>>>(shi, slo, woh, wol, bout, nullptr, out,
                                M, Vn, Hn, 1);
    }
}

// round 17
// speedup vs baseline: 4.7979x; 1.1752x over previous
#include <cuda_runtime.h>
#include <cuda_bf16.h>
#include <math.h>

// ---------------------------------------------------------------------------
// Problem dims (fixed by dataset): V=1024, E=256, H=512, B=64, S=2048
// ---------------------------------------------------------------------------
constexpr int Sn = 2048;
constexpr int Bn = 64;
constexpr int Hn = 512;
constexpr int En = 256;
constexpr int Vn = 1024;

constexpr int SCAN_CTAS = 128;                 // 8 b-groups x 16 j-groups
constexpr int SEQ_ELEMS = Sn * Bn * Hn;        // 67,108,864

// Scan smem: Ah[32][AP]h, Al[32][AP]h, Hs[8][HP]u32, Rd[8][136]f
// AP=520 (conflict-free A reads). HP=524: %4==0 -> uint4-aligned rows;
// mod 32 == 12 -> B-fragment reads hit 32 distinct banks.
constexpr int AP = 520;
constexpr int HP = 524;
constexpr int SCAN_SMEM = 32 * AP * 2 * 2 + 8 * HP * 4 + 8 * 136 * 4; // 87,680

// Device-global scratch (allocation-free per harness rules)
__device__ float          g_T[Vn * Hn];        // emb @ Wxh0^T + bxh0 + bhh0
__device__ float          g_A1[SEQ_ELEMS];     // layer-1 input term (fp32)
__device__ __nv_bfloat16  g_seqhi[SEQ_ELEMS];  // h sequence, bf16 hi part
__device__ __nv_bfloat16  g_seqlo[SEQ_ELEMS];  // h sequence, bf16 lo part
__device__ __nv_bfloat16  g_W1hi[Hn * Hn], g_W1lo[Hn * Hn];
__device__ __nv_bfloat16  g_Wohi[Vn * Hn], g_Wolo[Vn * Hn];
__device__ unsigned       g_hping[2 * Bn * Hn];  // packed bf16 (hi<<16|lo)
__device__ unsigned int   g_bars[8 * 32];        // per-group ctr, 128B padded

// Release-arrive / acquire-poll grid barrier primitives
__device__ __forceinline__ void bar_arrive_release(unsigned int* ctr) {
    unsigned old;
    asm volatile("atom.release.gpu.global.add.u32 %0, [%1], 1;"
                 : "=r"(old) : "l"(ctr) : "memory");
}
__device__ __forceinline__ unsigned bar_load_acquire(unsigned int* ctr) {
    unsigned v;
    asm volatile("ld.acquire.gpu.global.u32 %0, [%1];"
                 : "=r"(v) : "l"(ctr) : "memory");
    return v;
}

// bf16 mma: D(f32) += A(bf16 16x16) * B(bf16 16x8)   [sm_80 PTX]
__device__ __forceinline__ void mma_bf16(float* d, const unsigned* a,
                                         const unsigned* b) {
    asm volatile(
        "mma.sync.aligned.m16n8k16.row.col.f32.bf16.bf16.f32 "
        "{%0,%1,%2,%3}, {%4,%5,%6,%7}, {%8,%9}, {%0,%1,%2,%3};"
        : "+f"(d[0]), "+f"(d[1]), "+f"(d[2]), "+f"(d[3])
        : "r"(a[0]), "r"(a[1]), "r"(a[2]), "r"(a[3]),
          "r"(b[0]), "r"(b[1]));
}
__device__ __forceinline__ unsigned prmt(unsigned a, unsigned b, unsigned s) {
    unsigned d;
    asm("prmt.b32 %0, %1, %2, %3;" : "=r"(d) : "r"(a), "r"(b), "r"(s));
    return d;
}

// ---------------------------------------------------------------------------
// Init: reset barrier counters + zero packed hidden-state ping-pong
// ---------------------------------------------------------------------------
__global__ void scan_init() {
    unsigned i = blockIdx.x * blockDim.x + threadIdx.x;
    if (i < 8 * 32) g_bars[i] = 0u;
    for (unsigned k = i; k < 2u * Bn * Hn; k += gridDim.x * blockDim.x)
        g_hping[k] = 0u;
}

// Split fp32 -> (hi, lo) bf16 pair (weights prep)
__global__ void split_fp32(const float* __restrict__ src,
                           __nv_bfloat16* __restrict__ hi,
                           __nv_bfloat16* __restrict__ lo, int n) {
    const int i = blockIdx.x * 256 + threadIdx.x;
    if (i < n) {
        const float v = src[i];
        const __nv_bfloat16 h = __float2bfloat16_rn(v);
        hi[i] = h;
        lo[i] = __float2bfloat16_rn(v - __bfloat162float(h));
    }
}

// ---------------------------------------------------------------------------
// T[v][j] = sum_e emb[v][e] * Wxh0[j][e] + bxh0[j] + bhh0[j]
// ---------------------------------------------------------------------------
__global__ void __launch_bounds__(256) build_table(
    const float* __restrict__ emb, const float* __restrict__ Wxh0,
    const float* __restrict__ bxh0, const float* __restrict__ bhh0)
{
    __shared__ float es[En];
    const int v = blockIdx.x;
    const int tid = threadIdx.x;
    es[tid] = emb[(size_t)v * En + tid];
    __syncthreads();
    #pragma unroll
    for (int jj = 0; jj < 2; jj++) {
        const int j = tid + jj * 256;
        const float4* w = (const float4*)(Wxh0 + (size_t)j * En);
        float s = 0.0f;
        #pragma unroll 16
        for (int k = 0; k < En / 4; k++) {
            float4 wv = __ldg(&w[k]);
            s = fmaf(wv.x, es[4 * k + 0], s);
            s = fmaf(wv.y, es[4 * k + 1], s);
            s = fmaf(wv.z, es[4 * k + 2], s);
            s = fmaf(wv.w, es[4 * k + 3], s);
        }
        g_T[(size_t)v * Hn + j] = s + bxh0[j] + bhh0[j];
    }
}

// ---------------------------------------------------------------------------
// Tensor-core recurrent scan.
// CTA c: batch group grp=(c&7) -> b0=grp*8; j-group (c>>3) -> j0=(c>>3)*32.
// D[32j, 8b] = Whh_slice[32,512] (A, bf16 hi/lo resident in smem)
//            x h^T (B = 8 batch rows of 512 k, packed bf16 via L2 ping-pong).
// 8 warps = 2 j-tiles (m16) x 4 k-quarters (128 k); each warp: 8 ks-steps x
// 3 mma (AhiBhi + AhiBlo + AloBhi). 4-way k-reduction via padded smem;
// 256 threads map 1:1 to the 8b x 32j outputs. Per-group 16-CTA barrier.
// ---------------------------------------------------------------------------
__global__ void __launch_bounds__(256, 1) rnn_scan(
    const float* __restrict__ Whh,
    int mode,
    const int*   __restrict__ x,
    const float* __restrict__ T,
    const float* __restrict__ A1,
    __nv_bfloat16* __restrict__ seqhi,
    __nv_bfloat16* __restrict__ seqlo,
    float* __restrict__ hfinal)
{
    extern __shared__ char smraw[];
    unsigned short* Ah = (unsigned short*)smraw;            // [32][AP]
    unsigned short* Al = Ah + 32 * AP;                      // [32][AP]
    unsigned*       Hs = (unsigned*)(Al + 32 * AP);         // [8][HP]
    float*          Rd = (float*)(Hs + 8 * HP);             // [8][136]

    const int c    = blockIdx.x;
    const int grp  = c & 7;
    const int b0   = grp * 8;
    const int j0   = (c >> 3) * 32;
    const int tid  = threadIdx.x;
    const int w    = tid >> 5;
    const int l    = tid & 31;
    const int g    = l >> 2;                 // mma group (row / col n)
    const int tq   = l & 3;                  // thread-in-group
    const int jt   = w & 1;                  // j-tile (m16)
    const int kq   = w >> 1;                 // k-quarter (128 k)
    const int j_local = tid >> 3;            // 0..31  output j
    const int b_local = tid & 7;             // 0..7   output b
    const int ob = b0 + b_local;
    const int oj = j0 + j_local;
    unsigned int* ctr = &g_bars[grp * 32];

    // Convert this CTA's 32 Whh rows to bf16 hi/lo (resident all scan)
    for (int i = tid; i < 32 * Hn; i += 256) {
        const int r = i >> 9;
        const int k = i & 511;
        const float v = __ldg(&Whh[(size_t)(j0 + r) * Hn + k]);
        const __nv_bfloat16 h = __float2bfloat16_rn(v);
        const __nv_bfloat16 lo = __float2bfloat16_rn(v - __bfloat162float(h));
        Ah[r * AP + k] = *(const unsigned short*)&h;
        Al[r * AP + k] = *(const unsigned short*)&lo;
    }

    const int arow0 = jt * 16 + g;

    for (int t = 0; t < Sn; t++) {
        // Input term for this thread's output (independent of h staging)
        float base;
        if (mode == 0) {
            const int xv = x[(size_t)ob * Sn + t];
            base = __ldg(&T[(size_t)xv * Hn + oj]);
        } else {
            base = __ldcs(&A1[((size_t)t * Bn + ob) * Hn + oj]);
        }

        // Stage this group's 8 packed-h rows (16 KB) into smem
        const unsigned* hsrc = g_hping + (size_t)(t & 1) * (Bn * Hn)
                                       + (size_t)b0 * Hn;
        #pragma unroll
        for (int q = 0; q < 4; q++) {
            const int i   = tid + q * 256;        // 0..1023 uint4 slots
            const int row = i >> 7;
            const int c4  = (i & 127) << 2;
            uint4 v = __ldcg((const uint4*)(hsrc + row * Hn + c4));
            *(uint4*)(Hs + row * HP + c4) = v;    // HP%4==0 -> 16B aligned
        }
        __syncthreads();   // Hs (and, at t=0, Ah/Al) ready

        // Warp's m16n8 partial over its 128-k quarter
        float acc[4] = {0.f, 0.f, 0.f, 0.f};
        #pragma unroll
        for (int ks = 0; ks < 8; ks++) {
            const int kk = kq * 128 + ks * 16 + tq * 2;
            unsigned ah[4], al[4];
            ah[0] = *(const unsigned*)&Ah[(arow0    ) * AP + kk];
            ah[1] = *(const unsigned*)&Ah[(arow0 + 8) * AP + kk];
            ah[2] = *(const unsigned*)&Ah[(arow0    ) * AP + kk + 8];
            ah[3] = *(const unsigned*)&Ah[(arow0 + 8) * AP + kk + 8];
            al[0] = *(const unsigned*)&Al[(arow0    ) * AP + kk];
            al[1] = *(const unsigned*)&Al[(arow0 + 8) * AP + kk];
            al[2] = *(const unsigned*)&Al[(arow0    ) * AP + kk + 8];
            al[3] = *(const unsigned*)&Al[(arow0 + 8) * AP + kk + 8];

            const uint2 p0 = *(const uint2*)(Hs + g * HP + kk);
            const uint2 p1 = *(const uint2*)(Hs + g * HP + kk + 8);
            unsigned bh[2], bl[2];
            bh[0] = prmt(p0.x, p0.y, 0x7632u);   // (hi_k, hi_k+1)
            bl[0] = prmt(p0.x, p0.y, 0x5410u);   // (lo_k, lo_k+1)
            bh[1] = prmt(p1.x, p1.y, 0x7632u);
            bl[1] = prmt(p1.x, p1.y, 0x5410u);

            mma_bf16(acc, ah, bh);
            mma_bf16(acc, ah, bl);
            mma_bf16(acc, al, bh);
        }

        // Store partials: region (jt*4+kq), D row g/g+8 = j16, col 2tq = b
        {
            float* dst = Rd + (jt * 4 + kq) * 136;
            *(float2*)(dst + g * 8 + tq * 2)       = make_float2(acc[0], acc[1]);
            *(float2*)(dst + (g + 8) * 8 + tq * 2) = make_float2(acc[2], acc[3]);
        }
        __syncthreads();

        // 4-way k-reduction; thread -> output (j_local, b_local)
        const int jt2 = j_local >> 4;
        const int j16 = j_local & 15;
        float s = base;
        #pragma unroll
        for (int q = 0; q < 4; q++)
            s += Rd[(jt2 * 4 + q) * 136 + j16 * 8 + b_local];
        const float y = tanhf(s);

        // Emit: packed bf16 exchange + bf16 hi/lo sequence (+ final state)
        const __nv_bfloat16 yh = __float2bfloat16_rn(y);
        const __nv_bfloat16 yl = __float2bfloat16_rn(y - __bfloat162float(yh));
        const unsigned pk = ((unsigned)(*(const unsigned short*)&yh) << 16)
                          | (unsigned)(*(const unsigned short*)&yl);
        g_hping[(size_t)((t + 1) & 1) * (Bn * Hn) + (size_t)ob * Hn + oj] = pk;
        const size_t idx = ((size_t)t * Bn + ob) * Hn + oj;
        seqhi[idx] = yh;
        seqlo[idx] = yl;
        if (t == Sn - 1) hfinal[(size_t)ob * Hn + oj] = y;

        // Per-group 16-CTA barrier (release-arrive / acquire-poll)
        __syncthreads();                 // all stores + Rd reads done
        if (tid == 0) {
            bar_arrive_release(ctr);
            const unsigned target = (unsigned)(t + 1) * 16u;
            while (bar_load_acquire(ctr) < target) { }
        }
        __syncthreads();                 // release; guards Hs/Rd reuse
    }
}

// ---------------------------------------------------------------------------
// Split-bf16 tensor-core GEMM (HW-validated in R15):
//   C[M,N] = A[M,K] @ B[N,K]^T + bias1 (+bias2)
// ---------------------------------------------------------------------------
constexpr int GP = 40;   // smem row pitch in bf16 halves

__global__ void __launch_bounds__(256) gemm_mma(
    const __nv_bfloat16* __restrict__ Ahi_g,
    const __nv_bfloat16* __restrict__ Alo_g,
    const __nv_bfloat16* __restrict__ Bhi_g,
    const __nv_bfloat16* __restrict__ Blo_g,
    const float* __restrict__ bias1, const float* __restrict__ bias2,
    float* __restrict__ C, int M, int N, int K, int permuteOut)
{
    __shared__ __align__(16) unsigned short Ah[128 * GP], Al[128 * GP];
    __shared__ __align__(16) unsigned short Bh[128 * GP], Bl[128 * GP];

    const int tid = threadIdx.x;
    const int wid = tid >> 5, l = tid & 31;
    const int wm = wid >> 2, wn = wid & 3;
    const int g  = l >> 2,  tq = l & 3;
    const int row0 = blockIdx.y * 128;
    const int col0 = blockIdx.x * 128;

    const int lr = tid >> 1;
    const int ls = (tid & 1) * 2;

    float acc[4][4][4] = {};

    for (int kc = 0; kc < K; kc += 32) {
        __syncthreads();
        const size_t abase = (size_t)(row0 + lr) * K + kc;
        const size_t bbase = (size_t)(col0 + lr) * K + kc;
        #pragma unroll
        for (int s2 = 0; s2 < 2; s2++) {
            const int s = ls + s2;
            *(uint4*)&Ah[lr * GP + s * 8] =
                __ldg((const uint4*)(Ahi_g + abase + s * 8));
            *(uint4*)&Al[lr * GP + s * 8] =
                __ldg((const uint4*)(Alo_g + abase + s * 8));
            *(uint4*)&Bh[lr * GP + s * 8] =
                __ldg((const uint4*)(Bhi_g + bbase + s * 8));
            *(uint4*)&Bl[lr * GP + s * 8] =
                __ldg((const uint4*)(Blo_g + bbase + s * 8));
        }
        __syncthreads();

        #pragma unroll
        for (int ks = 0; ks < 32; ks += 16) {
            unsigned bh[4][2], bl[4][2];
            #pragma unroll
            for (int ni = 0; ni < 4; ni++) {
                const int boff = (wn * 32 + ni * 8 + g) * GP + ks + 2 * tq;
                bh[ni][0] = *(const unsigned*)&Bh[boff];
                bh[ni][1] = *(const unsigned*)&Bh[boff + 8];
                bl[ni][0] = *(const unsigned*)&Bl[boff];
                bl[ni][1] = *(const unsigned*)&Bl[boff + 8];
            }
            #pragma unroll
            for (int mi = 0; mi < 4; mi++) {
                const int aoff = (wm * 64 + mi * 16 + g) * GP + ks + 2 * tq;
                unsigned ah[4] = {
                    *(const unsigned*)&Ah[aoff],
                    *(const unsigned*)&Ah[aoff + 8 * GP],
                    *(const unsigned*)&Ah[aoff + 8],
                    *(const unsigned*)&Ah[aoff + 8 * GP + 8] };
                unsigned al[4] = {
                    *(const unsigned*)&Al[aoff],
                    *(const unsigned*)&Al[aoff + 8 * GP],
                    *(const unsigned*)&Al[aoff + 8],
                    *(const unsigned*)&Al[aoff + 8 * GP + 8] };
                #pragma unroll
                for (int ni = 0; ni < 4; ni++) {
                    mma_bf16(acc[mi][ni], ah, bh[ni]);
                    mma_bf16(acc[mi][ni], ah, bl[ni]);
                    mma_bf16(acc[mi][ni], al, bh[ni]);
                }
            }
        }
    }

    #pragma unroll
    for (int mi = 0; mi < 4; mi++) {
        #pragma unroll
        for (int rr = 0; rr < 2; rr++) {
            const int r = row0 + wm * 64 + mi * 16 + g + rr * 8;
            size_t basep;
            if (permuteOut) {
                const int bidx = r & (Bn - 1);
                const int tt   = r >> 6;
                basep = ((size_t)bidx * Sn + tt) * (size_t)N;
            } else {
                basep = (size_t)r * (size_t)N;
            }
            #pragma unroll
            for (int ni = 0; ni < 4; ni++) {
                const int n = col0 + wn * 32 + ni * 8 + 2 * tq;
                float b0v = bias1 ? __ldg(&bias1[n])     : 0.0f;
                float b1v = bias1 ? __ldg(&bias1[n + 1]) : 0.0f;
                if (bias2) {
                    b0v += __ldg(&bias2[n]);
                    b1v += __ldg(&bias2[n + 1]);
                }
                float2 v;
                v.x = acc[mi][ni][rr * 2 + 0] + b0v;
                v.y = acc[mi][ni][rr * 2 + 1] + b1v;
                *(float2*)(C + basep + n) = v;
            }
        }
    }
}

// ---------------------------------------------------------------------------
// Launch: 9 graph nodes. Output layout: logits[B,S,V], h0[B,H], h1[B,H].
// ---------------------------------------------------------------------------
extern "C" void kernel_launch(void* const* d_in, const int* in_sizes, int n_in,
                              void* d_out, int out_size) {
    const int*   x    = (const int*)  d_in[0];
    const float* emb  = (const float*)d_in[1];
    const float* Wxh0 = (const float*)d_in[2];
    const float* bxh0 = (const float*)d_in[3];
    const float* Whh0 = (const float*)d_in[4];
    const float* bhh0 = (const float*)d_in[5];
    const float* Wxh1 = (const float*)d_in[6];
    const float* bxh1 = (const float*)d_in[7];
    const float* Whh1 = (const float*)d_in[8];
    const float* bhh1 = (const float*)d_in[9];
    const float* Wout = (const float*)d_in[10];
    const float* bout = (const float*)d_in[11];
    float* out = (float*)d_out;

    void* p;
    cudaGetSymbolAddress(&p, g_A1);    float* A1 = (float*)p;
    cudaGetSymbolAddress(&p, g_T);     float* Tt = (float*)p;
    cudaGetSymbolAddress(&p, g_seqhi); __nv_bfloat16* shi = (__nv_bfloat16*)p;
    cudaGetSymbolAddress(&p, g_seqlo); __nv_bfloat16* slo = (__nv_bfloat16*)p;
    cudaGetSymbolAddress(&p, g_W1hi);  __nv_bfloat16* w1h = (__nv_bfloat16*)p;
    cudaGetSymbolAddress(&p, g_W1lo);  __nv_bfloat16* w1l = (__nv_bfloat16*)p;
    cudaGetSymbolAddress(&p, g_Wohi);  __nv_bfloat16* woh = (__nv_bfloat16*)p;
    cudaGetSymbolAddress(&p, g_Wolo);  __nv_bfloat16* wol = (__nv_bfloat16*)p;

    cudaFuncSetAttribute(rnn_scan,
                         cudaFuncAttributeMaxDynamicSharedMemorySize,
                         SCAN_SMEM);

    const size_t logitsElems = (size_t)Bn * Sn * Vn;
    float* hf0 = out + logitsElems;
    float* hf1 = out + logitsElems + (size_t)Bn * Hn;
    const int M = Bn * Sn;

    // 1) Fused embedding + input-projection table; weight splits
    build_table<<<Vn, 256>>>(emb, Wxh0, bxh0, bhh0);
    split_fp32<<<(Hn * Hn + 255) / 256, 256>>>(Wxh1, w1h, w1l, Hn * Hn);
    split_fp32<<<(Vn * Hn + 255) / 256, 256>>>(Wout, woh, wol, Vn * Hn);

    // 2) Layer-0 scan (tensor-core) -> seq hi/lo
    scan_init<<<64, 256>>>();
    rnn_scan<<<SCAN_CTAS, 256, SCAN_SMEM>>>(Whh0, 0, x, Tt, nullptr,
                                            shi, slo, hf0);

    // 3) A1 = seq0 @ Wxh1^T + bxh1 + bhh1  (tensor-core split-bf16)
    {
        dim3 grid(Hn / 128, M / 128);
        gemm_mma<<<grid, 256>>>(shi, slo, w1h, w1l, bxh1, bhh1, A1,
                                M, Hn, Hn, 0);
    }

    // 4) Layer-1 scan (overwrites seq hi/lo with h1 sequence)
    scan_init<<<64, 256>>>();
    rnn_scan<<<SCAN_CTAS, 256, SCAN_SMEM>>>(Whh1, 1, x, Tt, A1,
                                            shi, slo, hf1);

    // 5) logits = seq1 @ Wout^T + bout, permuted to [B,S,V]
    {
        dim3 grid(Vn / 128, M / 128);
        gemm_mma<<<grid, 256>>>(shi, slo, woh, wol, bout, nullptr, out,
                                M, Vn, Hn, 1);
    }
}